// round 13
// baseline (speedup 1.0000x reference)
#include <cuda_runtime.h>
#include <math.h>

#define NROWS   65536
#define DDIM    64
#define TROWS   16            /* rows per tile */
#define NTILE   4096          /* NROWS / TROWS */
#define PBLK    148           /* persistent blocks, 1 per SM */
#define NTHR    512
#define NWORK   8             /* 2-warp workers per block */
#define NSTEPS  128
#define TSZ     1024          /* TROWS * DDIM floats per tile (global layout) */
#define SSTR    68            /* padded smem row stride (floats), 16B-aligned, 272B%128=16 */
#define ASZ     (TROWS * SSTR)  /* 1088 floats per smem tile array */

/* shared memory layout (float offsets) */
#define OFF_SB    0            /* 64 : bias */
#define OFF_CLAIM 64           /* 8 unsigned claim slots (+pad) */
#define OFF_W2    80           /* 4096 : W repacked */
#define OFF_H0    4176         /* per-worker regions */
#define H_SYI0    0
#define H_SYI1    ASZ
#define H_SK      (2 * ASZ)             /* 4 slots (k3..k6) x ASZ */
#define H_RED     (6 * ASZ)             /* 2 doubles */
#define H_STRIDE  (6 * ASZ + 8)
#define SMEM_FLOATS (OFF_H0 + NWORK * H_STRIDE)
#define SMEM_BYTES  (SMEM_FLOATS * 4)

typedef unsigned long long ull;

/* ---------------- persistent device state (no allocations) ---------------- */
__device__ float    g_Ya[NROWS * DDIM];
__device__ float    g_Yb[NROWS * DDIM];
__device__ float    g_Ka[NROWS * DDIM];
__device__ float    g_Kb[NROWS * DDIM];
__device__ double   g_tpart[NTILE];
__device__ unsigned g_tctr[NSTEPS];
__device__ unsigned g_count;
__device__ unsigned g_release;

/* Dormand-Prince A coefficients (exact float32 of rationals) */
__constant__ float cA[6][6] = {
  { (float)(1.0/5.0), 0.f, 0.f, 0.f, 0.f, 0.f },
  { (float)(3.0/40.0), (float)(9.0/40.0), 0.f, 0.f, 0.f, 0.f },
  { (float)(44.0/45.0), (float)(-56.0/15.0), (float)(32.0/9.0), 0.f, 0.f, 0.f },
  { (float)(19372.0/6561.0), (float)(-25360.0/2187.0), (float)(64448.0/6561.0), (float)(-212.0/729.0), 0.f, 0.f },
  { (float)(9017.0/3168.0), (float)(-355.0/33.0), (float)(46732.0/5247.0), (float)(49.0/176.0), (float)(-5103.0/18656.0), 0.f },
  { (float)(35.0/384.0), 0.f, (float)(500.0/1113.0), (float)(125.0/192.0), (float)(-2187.0/6784.0), (float)(11.0/84.0) },
};

union F4U {
  float v[4];
  ull   q[2];
  float4 f4;
};

__device__ __forceinline__ F4U ld4u(const float* p) { F4U r; r.f4 = *(const float4*)p; return r; }
__device__ __forceinline__ void st4u(float* p, const F4U a) { *(float4*)p = a.f4; }
__device__ __forceinline__ F4U ld4cg(const float* p) {
  F4U r;
  asm volatile("ld.global.cg.v4.f32 {%0,%1,%2,%3}, [%4];"
               : "=f"(r.v[0]), "=f"(r.v[1]), "=f"(r.v[2]), "=f"(r.v[3]) : "l"(p));
  return r;
}
__device__ __forceinline__ double lddcg(const double* p) {
  double r;
  asm volatile("ld.global.cg.f64 %0, [%1];" : "=d"(r) : "l"(p));
  return r;
}

/* packed fp32x2 ops (Blackwell) */
__device__ __forceinline__ ull fma2(ull a, ull b, ull c) {
  ull d; asm("fma.rn.f32x2 %0, %1, %2, %3;" : "=l"(d) : "l"(a), "l"(b), "l"(c)); return d;
}
__device__ __forceinline__ ull mul2(ull a, ull b) {
  ull d; asm("mul.rn.f32x2 %0, %1, %2;" : "=l"(d) : "l"(a), "l"(b)); return d;
}
__device__ __forceinline__ ull pack2(float x) {
  ull d; asm("mov.b64 %0, {%1, %1};" : "=l"(d) : "f"(x)); return d;
}
__device__ __forceinline__ void unpack2(ull v, float& lo, float& hi) {
  asm("mov.b64 {%0, %1}, %2;" : "=f"(lo), "=f"(hi) : "l"(v));
}
/* fast sin: args O(1..10); abs err ~2^-21, far below 1e-3 tolerance */
__device__ __forceinline__ float fsin(float x) {
  float r; asm("sin.approx.f32 %0, %1;" : "=f"(r) : "f"(x)); return r;
}
/* worker named barrier (ids 1..8, 64 threads) */
__device__ __forceinline__ void barw(int wk) {
  asm volatile("bar.sync %0, 64;" :: "r"(wk + 1) : "memory");
}

/* 4x4-output 64-k GEMM via fma.rn.f32x2 on a 16-row smem tile (stride SSTR).
   Thread rows: rbase + 4*i (rbase 0..3); cols cbg*4..+3 (cbg = w*8 + lane&7).
   a-loads: 4 distinct rbase windows {0,16,32,48}B -> conflict-free, 1 wf.
   W-loads: 8 cbg x 16B = 128B aligned contiguous per warp -> 1 wf. */
__device__ __forceinline__ void gemm4x4(const float* __restrict__ sa,
                                        const float* __restrict__ sW2,
                                        int rbase, int cbg, float accf[4][4]) {
  ull acc[4][4];
#pragma unroll
  for (int i = 0; i < 4; ++i)
#pragma unroll
    for (int j = 0; j < 4; ++j) acc[i][j] = 0ull;

  const float* ap = sa + rbase * SSTR;
#pragma unroll
  for (int k4 = 0; k4 < 16; ++k4) {
    ulonglong2 av[4];
#pragma unroll
    for (int i = 0; i < 4; ++i)
      av[i] = *(const ulonglong2*)(ap + i * 4 * SSTR + k4 * 4);
#pragma unroll
    for (int hh = 0; hh < 2; ++hh) {
      const int k2i = k4 * 2 + hh;
      ulonglong2 w01 = *(const ulonglong2*)(sW2 + k2i * 128 + cbg * 4);
      ulonglong2 w23 = *(const ulonglong2*)(sW2 + k2i * 128 + 64 + cbg * 4);
#pragma unroll
      for (int i = 0; i < 4; ++i) {
        ull a = hh ? av[i].y : av[i].x;
        acc[i][0] = fma2(a, w01.x, acc[i][0]);
        acc[i][1] = fma2(a, w01.y, acc[i][1]);
        acc[i][2] = fma2(a, w23.x, acc[i][2]);
        acc[i][3] = fma2(a, w23.y, acc[i][3]);
      }
    }
  }
#pragma unroll
  for (int i = 0; i < 4; ++i)
#pragma unroll
    for (int j = 0; j < 4; ++j) {
      float lo, hi; unpack2(acc[i][j], lo, hi);
      accf[i][j] = lo + hi;
    }
}

__global__ void init_kernel() {
  if (threadIdx.x == 0) { g_count = 0u; g_release = 0u; }
  if (threadIdx.x < NSTEPS) g_tctr[threadIdx.x] = 0u;
}

/* ---------------- the whole solve in one persistent kernel ---------------- */
__global__ void __launch_bounds__(NTHR, 1) ode_kernel(const float* __restrict__ x,
                                                      const float* __restrict__ W,
                                                      const float* __restrict__ b,
                                                      float* __restrict__ out) {
  extern __shared__ float sm[];
  float* sb  = sm + OFF_SB;
  float* sW2 = sm + OFF_W2;
  unsigned* sclaim = (unsigned*)(sm + OFF_CLAIM);

  const int tid = threadIdx.x, bid = blockIdx.x;
  const int wk = tid >> 6, t64 = tid & 63;        /* 2-warp worker, thread in worker */
  const int w = (tid >> 5) & 1;                   /* warp within worker: col half */
  const int lane = tid & 31;
  float* smq  = sm + OFF_H0 + wk * H_STRIDE;
  float* syi0 = smq + H_SYI0;
  float* syi1 = smq + H_SYI1;
  float* sk   = smq + H_SK;          /* slots: 0=k3 1=k4 2=k5 3=k6 (stride-68 tile layout) */
  double* red = (double*)(smq + H_RED);

  const int rbase = lane >> 3;           /* 0..3; thread rows rbase + 4*r */
  const int cbg   = w * 8 + (lane & 7);  /* 0..15; cols cbg*4..+3 */
  int ogr[4], osr[4];
#pragma unroll
  for (int r = 0; r < 4; ++r) {
    const int row = rbase + 4 * r;
    ogr[r] = row * DDIM + cbg * 4;     /* global (dense) */
    osr[r] = row * SSTR + cbg * 4;     /* smem (padded) */
  }

  if (tid < 16) st4u(&sb[tid * 4], ld4u(&b[tid * 4]));
  /* repack W into k-pair-major layout (validated R3-R12) */
  for (int p = tid; p < 2048; p += NTHR) {
    const int k2i = p >> 6, j = p & 63;
    const int cbb = j >> 2, jr = j & 3;
    const int pos = k2i * 128 + ((jr >= 2) ? 64 : 0) + cbb * 4 + (jr & 1) * 2;
    sW2[pos]     = W[j * DDIM + 2 * k2i];
    sW2[pos + 1] = W[j * DDIM + 2 * k2i + 1];
  }
  __syncthreads();
  const F4U bb = ld4u(&sb[cbg * 4]);

  /* prologue: Ya = x ; Ka = k1 = f(x).  Static tiles per worker. */
  for (int t = bid * NWORK + wk; t < NTILE; t += PBLK * NWORK) {
    const size_t base = (size_t)t * TSZ;
    for (int i = t64; i < TSZ / 4; i += 64) {
      const int row = i >> 4, c4 = i & 15;
      F4U v = ld4u(&x[base + i * 4]);
      st4u(&syi0[row * SSTR + c4 * 4], v);
      st4u(&g_Ya[base + i * 4], v);
    }
    barw(wk);
    float acc[4][4];
    gemm4x4(syi0, sW2, rbase, cbg, acc);
#pragma unroll
    for (int r = 0; r < 4; ++r) {
      F4U kv;
#pragma unroll
      for (int j = 0; j < 4; ++j) kv.v[j] = fsin(-(acc[r][j] + bb.v[j]));
      st4u(&g_Ka[base + ogr[r]], kv);
    }
    barw(wk);
  }

  unsigned nbar = 1;
  __syncthreads();
  if (tid == 0) {
    __threadfence();
    unsigned old = atomicAdd(&g_count, 1u);
    if (old == PBLK - 1) { atomicExch(&g_count, 0u); __threadfence(); atomicExch(&g_release, nbar); }
    else { while (*((volatile unsigned*)&g_release) < nbar) { } }
    __threadfence();
  }
  __syncthreads();

  float t_now = 0.0f, h = 0.01f, h_eff = 0.01f;
  int sel = 0, done = 0;

  const float E0 = (float)(71.0 / 57600.0);
  const float E2 = (float)(-71.0 / 16695.0);
  const float E3 = (float)(71.0 / 1920.0);
  const float E4 = (float)(-17253.0 / 339200.0);
  const float E5 = (float)(22.0 / 525.0);
  const float E6 = (float)(-1.0 / 40.0);
  const float ATOL = 1e-5f, RTOL = 1e-5f;

  for (int step = 0; step < NSTEPS; ++step) {
    if (done) break;
    const float* __restrict__ Yg = sel ? g_Yb : g_Ya;
    const float* __restrict__ Kg = sel ? g_Kb : g_Ka;
    float* __restrict__ Yo = sel ? g_Ya : g_Yb;
    float* __restrict__ Ko = sel ? g_Ka : g_Kb;
    const ull h2 = pack2(h_eff);

    /* ---- work-stealing tile loop (per 2-warp worker) ---- */
    if (t64 == 0) sclaim[wk] = atomicAdd(&g_tctr[step], 1u);
    barw(wk);
    unsigned tt = sclaim[wk];
    barw(wk);

    while (tt < NTILE) {
      const size_t base = (size_t)tt * TSZ;

      /* own y, k1, k2 in registers */
      F4U yq[4], k1r[4], k2r[4], y5r[4], eac[4];
#pragma unroll
      for (int r = 0; r < 4; ++r) {
        yq[r]  = ld4cg(&Yg[base + ogr[r]]);
        k1r[r] = ld4cg(&Kg[base + ogr[r]]);
      }

      float acc[4][4];
      /* ---- stages 1..5 (rolled; one 64-thread barrier per stage) ---- */
      for (int st = 1; st <= 5; ++st) {
        float* syiW = (st & 1) ? syi1 : syi0;
        const ull c0 = pack2(cA[st - 1][0]);
        const ull c1 = pack2(cA[st - 1][1]);
#pragma unroll
        for (int r = 0; r < 4; ++r) {
          ull s0 = mul2(c0, k1r[r].q[0]);
          ull s1 = mul2(c0, k1r[r].q[1]);
          if (st >= 2) {                      /* k2 from registers */
            s0 = fma2(c1, k2r[r].q[0], s0);
            s1 = fma2(c1, k2r[r].q[1], s1);
          }
          for (int m = 0; m < st - 2; ++m) {  /* k3..k_st from smem (same-thread) */
            const ull cm = pack2(cA[st - 1][m + 2]);
            F4U kv = ld4u(&sk[m * ASZ + osr[r]]);
            s0 = fma2(cm, kv.q[0], s0);
            s1 = fma2(cm, kv.q[1], s1);
          }
          F4U yiv;
          yiv.q[0] = fma2(h2, s0, yq[r].q[0]);
          yiv.q[1] = fma2(h2, s1, yq[r].q[1]);
          st4u(&syiW[osr[r]], yiv);
        }
        barw(wk);                  /* cross-warp: both col-halves of yi visible */

        gemm4x4(syiW, sW2, rbase, cbg, acc);

        if (st == 1) {
#pragma unroll
          for (int r = 0; r < 4; ++r)
#pragma unroll
            for (int j = 0; j < 4; ++j) k2r[r].v[j] = fsin(-(acc[r][j] + bb.v[j]));
        } else {
#pragma unroll
          for (int r = 0; r < 4; ++r) {
            F4U kv;
#pragma unroll
            for (int j = 0; j < 4; ++j) kv.v[j] = fsin(-(acc[r][j] + bb.v[j]));
            st4u(&sk[(st - 2) * ASZ + osr[r]], kv);   /* same-thread slot */
          }
        }
        /* no second barrier: double-buffered syi covers the WAR hazard */
      }

      /* ---- stage 6 (peeled, fused with error accumulation) ---- */
      {
        const ull C1 = pack2((float)(35.0 / 384.0));
        const ull C3 = pack2((float)(500.0 / 1113.0));
        const ull C4 = pack2((float)(125.0 / 192.0));
        const ull C5 = pack2((float)(-2187.0 / 6784.0));
        const ull C6 = pack2((float)(11.0 / 84.0));
        const ull F0 = pack2(E0), F2 = pack2(E2), F3 = pack2(E3);
        const ull F4c = pack2(E4), F5 = pack2(E5);
#pragma unroll
        for (int r = 0; r < 4; ++r) {
          F4U k3 = ld4u(&sk[0 * ASZ + osr[r]]);
          F4U k4 = ld4u(&sk[1 * ASZ + osr[r]]);
          F4U k5 = ld4u(&sk[2 * ASZ + osr[r]]);
          F4U k6 = ld4u(&sk[3 * ASZ + osr[r]]);
#pragma unroll
          for (int q = 0; q < 2; ++q) {
            ull s = mul2(C1, k1r[r].q[q]);       /* B5: k2 coeff = 0 */
            s = fma2(C3, k3.q[q], s);
            s = fma2(C4, k4.q[q], s);
            s = fma2(C5, k5.q[q], s);
            s = fma2(C6, k6.q[q], s);
            y5r[r].q[q] = fma2(h2, s, yq[r].q[q]);
            ull e = mul2(F0, k1r[r].q[q]);       /* E1 = 0 */
            e = fma2(F2, k3.q[q], e);
            e = fma2(F3, k4.q[q], e);
            e = fma2(F4c, k5.q[q], e);
            e = fma2(F5, k6.q[q], e);
            eac[r].q[q] = e;
          }
          st4u(&syi0[osr[r]], y5r[r]);           /* y5 is stage-6 input (FSAL) */
          st4u(&Yo[base + ogr[r]], y5r[r]);      /* candidate y5 out */
        }
        barw(wk);

        gemm4x4(syi0, sW2, rbase, cbg, acc);
      }

      /* k7 + error finalize + FSAL */
      double lsum = 0.0;
#pragma unroll
      for (int r = 0; r < 4; ++r) {
        F4U k7;
#pragma unroll
        for (int j = 0; j < 4; ++j) k7.v[j] = fsin(-(acc[r][j] + bb.v[j]));
        st4u(&Ko[base + ogr[r]], k7);
#pragma unroll
        for (int j = 0; j < 4; ++j) {
          float e = fmaf(E6, k7.v[j], eac[r].v[j]);
          e *= h_eff;
          float scale = fmaf(RTOL, fmaxf(fabsf(yq[r].v[j]), fabsf(y5r[r].v[j])), ATOL);
          float rr = e / scale;
          lsum += (double)(rr * rr);
        }
      }

      /* claim next tile (folded into epilogue barrier) */
      if (t64 == 0) sclaim[wk] = atomicAdd(&g_tctr[step], 1u);

      /* deterministic per-tile reduce (warp shuffle + 2-term fixed sum) */
#pragma unroll
      for (int off = 16; off > 0; off >>= 1)
        lsum += __shfl_down_sync(0xffffffffu, lsum, off);
      if (lane == 0) red[w] = lsum;
      barw(wk);
      unsigned nx = sclaim[wk];
      if (t64 == 0) {
        g_tpart[tt] = red[0] + red[1];
        __threadfence();
      }
      barw(wk);
      tt = nx;
    }

    /* ---- grid barrier ---- */
    ++nbar;
    __syncthreads();
    if (tid == 0) {
      __threadfence();
      unsigned old = atomicAdd(&g_count, 1u);
      if (old == PBLK - 1) { atomicExch(&g_count, 0u); __threadfence(); atomicExch(&g_release, nbar); }
      else { while (*((volatile unsigned*)&g_release) < nbar) { } }
      __threadfence();
    }
    __syncthreads();

    /* ---- deterministic control: fixed-order sum of 4096 tile partials ---- */
    double* sdd = (double*)(sm + OFF_H0);
    {
      double s = 0.0;
#pragma unroll
      for (int k = 0; k < 8; ++k) s += lddcg(&g_tpart[8 * tid + k]);
      sdd[tid] = s;
    }
    __syncthreads();
#pragma unroll
    for (int off = NTHR / 2; off > 0; off >>= 1) {
      if (tid < off) sdd[tid] += sdd[tid + off];
      __syncthreads();
    }
    const float err_norm = sqrtf((float)(sdd[0] / (double)((double)NROWS * (double)DDIM)));
    __syncthreads();

    /* exact reference control law (redundant in every thread/block) */
    const int accept = (err_norm <= 1.0f);
    if (accept) { t_now += h_eff; sel ^= 1; }
    float factor = 0.9f * powf(fmaxf(err_norm, 1e-10f), -0.2f);
    factor = fminf(fmaxf(factor, 0.2f), 10.0f);
    h = h_eff * factor;
    const float remaining = 5.0f - t_now;
    done = (remaining <= 0.0f) ? 1 : 0;
    h_eff = fminf(h, fmaxf(remaining, 1e-12f));
  }

  /* write accepted buffer to output (grid-stride, .cg: bypass stale L1) */
  const float* __restrict__ Yf = sel ? g_Yb : g_Ya;
  for (size_t i = (size_t)bid * NTHR + tid; i < (size_t)NROWS * DDIM / 4; i += (size_t)PBLK * NTHR) {
    F4U v = ld4cg(&Yf[i * 4]);
    st4u(&out[i * 4], v);
  }
}

extern "C" void kernel_launch(void* const* d_in, const int* in_sizes, int n_in,
                              void* d_out, int out_size) {
  const float* x = (const float*)d_in[0];
  const float* W = (const float*)d_in[1];
  const float* b = (const float*)d_in[2];
  float* out = (float*)d_out;

  cudaFuncSetAttribute(ode_kernel, cudaFuncAttributeMaxDynamicSharedMemorySize, SMEM_BYTES);

  init_kernel<<<1, 128>>>();
  ode_kernel<<<PBLK, NTHR, SMEM_BYTES>>>(x, W, b, out);
}

// round 14
// speedup vs baseline: 1.0674x; 1.0674x over previous
#include <cuda_runtime.h>
#include <math.h>

#define NROWS   65536
#define DDIM    64
#define TROWS   8             /* rows per tile */
#define NTILE   8192          /* NROWS / TROWS */
#define PBLK    148           /* persistent blocks, 1 per SM */
#define NTHR    512
#define NWORK   16            /* warp-workers per block */
#define NSTEPS  128
#define TSZ     512           /* TROWS * DDIM floats per tile */

/* shared memory layout (float offsets) */
#define OFF_SB    0            /* 64 : bias */
#define OFF_W2    80           /* 4096 : W repacked */
#define OFF_H0    4176         /* per-worker regions */
#define H_SYI0    0
#define H_SYI1    TSZ
#define H_SK      (2 * TSZ)             /* 4 slots (k3..k6) x 512 */
#define H_STRIDE  (6 * TSZ)
#define SMEM_FLOATS (OFF_H0 + NWORK * H_STRIDE)
#define SMEM_BYTES  (SMEM_FLOATS * 4)

typedef unsigned long long ull;

/* ---------------- persistent device state (no allocations) ---------------- */
__device__ float    g_Ya[NROWS * DDIM];
__device__ float    g_Yb[NROWS * DDIM];
__device__ float    g_Ka[NROWS * DDIM];
__device__ float    g_Kb[NROWS * DDIM];
__device__ double   g_tpart[NTILE];
__device__ unsigned g_tctr[NSTEPS];
__device__ unsigned g_count;
__device__ unsigned g_release;

/* Dormand-Prince A coefficients (exact float32 of rationals) */
__constant__ float cA[6][6] = {
  { (float)(1.0/5.0), 0.f, 0.f, 0.f, 0.f, 0.f },
  { (float)(3.0/40.0), (float)(9.0/40.0), 0.f, 0.f, 0.f, 0.f },
  { (float)(44.0/45.0), (float)(-56.0/15.0), (float)(32.0/9.0), 0.f, 0.f, 0.f },
  { (float)(19372.0/6561.0), (float)(-25360.0/2187.0), (float)(64448.0/6561.0), (float)(-212.0/729.0), 0.f, 0.f },
  { (float)(9017.0/3168.0), (float)(-355.0/33.0), (float)(46732.0/5247.0), (float)(49.0/176.0), (float)(-5103.0/18656.0), 0.f },
  { (float)(35.0/384.0), 0.f, (float)(500.0/1113.0), (float)(125.0/192.0), (float)(-2187.0/6784.0), (float)(11.0/84.0) },
};

union F4U {
  float v[4];
  ull   q[2];
  float4 f4;
};

__device__ __forceinline__ F4U ld4u(const float* p) { F4U r; r.f4 = *(const float4*)p; return r; }
__device__ __forceinline__ void st4u(float* p, const F4U a) { *(float4*)p = a.f4; }
__device__ __forceinline__ F4U ld4cg(const float* p) {
  F4U r;
  asm volatile("ld.global.cg.v4.f32 {%0,%1,%2,%3}, [%4];"
               : "=f"(r.v[0]), "=f"(r.v[1]), "=f"(r.v[2]), "=f"(r.v[3]) : "l"(p));
  return r;
}
__device__ __forceinline__ double lddcg(const double* p) {
  double r;
  asm volatile("ld.global.cg.f64 %0, [%1];" : "=d"(r) : "l"(p));
  return r;
}

/* packed fp32x2 ops (Blackwell) */
__device__ __forceinline__ ull fma2(ull a, ull b, ull c) {
  ull d; asm("fma.rn.f32x2 %0, %1, %2, %3;" : "=l"(d) : "l"(a), "l"(b), "l"(c)); return d;
}
__device__ __forceinline__ ull mul2(ull a, ull b) {
  ull d; asm("mul.rn.f32x2 %0, %1, %2;" : "=l"(d) : "l"(a), "l"(b)); return d;
}
__device__ __forceinline__ ull pack2(float x) {
  ull d; asm("mov.b64 %0, {%1, %1};" : "=l"(d) : "f"(x)); return d;
}
__device__ __forceinline__ void unpack2(ull v, float& lo, float& hi) {
  asm("mov.b64 {%0, %1}, %2;" : "=f"(lo), "=f"(hi) : "l"(v));
}
/* fast sin: args O(1..10); abs err ~2^-21, far below 1e-3 tolerance */
__device__ __forceinline__ float fsin(float x) {
  float r; asm("sin.approx.f32 %0, %1;" : "=f"(r) : "f"(x)); return r;
}

/* 4x4-output 64-k GEMM via fma.rn.f32x2 (R12 layout — validated best). */
__device__ __forceinline__ void gemm4x4(const float* __restrict__ sa,
                                        const float* __restrict__ sW2,
                                        int r0, int cbg, float accf[4][4]) {
  ull acc[4][4];
#pragma unroll
  for (int i = 0; i < 4; ++i)
#pragma unroll
    for (int j = 0; j < 4; ++j) acc[i][j] = 0ull;

  const float* ap = sa + r0 * DDIM;
#pragma unroll
  for (int k4 = 0; k4 < 16; ++k4) {
    ulonglong2 av[4];
#pragma unroll
    for (int i = 0; i < 4; ++i)
      av[i] = *(const ulonglong2*)(ap + i * DDIM + k4 * 4);
#pragma unroll
    for (int hh = 0; hh < 2; ++hh) {
      const int k2i = k4 * 2 + hh;
      ulonglong2 w01 = *(const ulonglong2*)(sW2 + k2i * 128 + cbg * 4);
      ulonglong2 w23 = *(const ulonglong2*)(sW2 + k2i * 128 + 64 + cbg * 4);
#pragma unroll
      for (int i = 0; i < 4; ++i) {
        ull a = hh ? av[i].y : av[i].x;
        acc[i][0] = fma2(a, w01.x, acc[i][0]);
        acc[i][1] = fma2(a, w01.y, acc[i][1]);
        acc[i][2] = fma2(a, w23.x, acc[i][2]);
        acc[i][3] = fma2(a, w23.y, acc[i][3]);
      }
    }
  }
#pragma unroll
  for (int i = 0; i < 4; ++i)
#pragma unroll
    for (int j = 0; j < 4; ++j) {
      float lo, hi; unpack2(acc[i][j], lo, hi);
      accf[i][j] = lo + hi;
    }
}

__global__ void init_kernel() {
  if (threadIdx.x == 0) { g_count = 0u; g_release = 0u; }
  if (threadIdx.x < NSTEPS) g_tctr[threadIdx.x] = 0u;
}

/* ---------------- the whole solve in one persistent kernel ---------------- */
__global__ void __launch_bounds__(NTHR, 1) ode_kernel(const float* __restrict__ x,
                                                      const float* __restrict__ W,
                                                      const float* __restrict__ b,
                                                      float* __restrict__ out) {
  extern __shared__ float sm[];
  float* sb  = sm + OFF_SB;
  float* sW2 = sm + OFF_W2;

  const int tid = threadIdx.x, bid = blockIdx.x;
  const int wrk = tid >> 5, lane = tid & 31;      /* warp-worker id, lane */
  float* smq  = sm + OFF_H0 + wrk * H_STRIDE;
  float* syi0 = smq + H_SYI0;
  float* syi1 = smq + H_SYI1;
  float* sk   = smq + H_SK;          /* slots: 0=k3 1=k4 2=k5 3=k6 */

  const int r0  = (lane >> 4) << 2;      /* rows r0..r0+3 (0 or 4) */
  const int cbg = lane & 15;             /* cols cbg*4..+3 */
  const int og  = r0 * DDIM + cbg * 4;   /* own base offset within tile */

  if (tid < 16) st4u(&sb[tid * 4], ld4u(&b[tid * 4]));
  /* repack W into k-pair-major layout (validated R3-R13) */
  for (int p = tid; p < 2048; p += NTHR) {
    const int k2i = p >> 6, j = p & 63;
    const int cbb = j >> 2, jr = j & 3;
    const int pos = k2i * 128 + ((jr >= 2) ? 64 : 0) + cbb * 4 + (jr & 1) * 2;
    sW2[pos]     = W[j * DDIM + 2 * k2i];
    sW2[pos + 1] = W[j * DDIM + 2 * k2i + 1];
  }
  __syncthreads();
  const F4U bb = ld4u(&sb[cbg * 4]);

  /* prologue: Ya = x ; Ka = k1 = f(x).  Static tiles per warp-worker. */
  for (int t = bid * NWORK + wrk; t < NTILE; t += PBLK * NWORK) {
    const size_t base = (size_t)t * TSZ;
    for (int i = lane; i < TSZ / 4; i += 32) {
      F4U v = ld4u(&x[base + i * 4]);
      st4u(&syi0[i * 4], v);
      st4u(&g_Ya[base + i * 4], v);
    }
    __syncwarp();
    float acc[4][4];
    gemm4x4(syi0, sW2, r0, cbg, acc);
#pragma unroll
    for (int r = 0; r < 4; ++r) {
      F4U kv;
#pragma unroll
      for (int j = 0; j < 4; ++j) kv.v[j] = fsin(-(acc[r][j] + bb.v[j]));
      st4u(&g_Ka[base + og + r * DDIM], kv);
    }
    __syncwarp();
  }

  unsigned nbar = 1;
  __syncthreads();
  if (tid == 0) {
    __threadfence();
    unsigned old = atomicAdd(&g_count, 1u);
    if (old == PBLK - 1) { atomicExch(&g_count, 0u); __threadfence(); atomicExch(&g_release, nbar); }
    else { while (*((volatile unsigned*)&g_release) < nbar) { } }
    __threadfence();
  }
  __syncthreads();

  float t_now = 0.0f, h = 0.01f, h_eff = 0.01f;
  int sel = 0, done = 0;

  const float E0 = (float)(71.0 / 57600.0);
  const float E2 = (float)(-71.0 / 16695.0);
  const float E3 = (float)(71.0 / 1920.0);
  const float E4 = (float)(-17253.0 / 339200.0);
  const float E5 = (float)(22.0 / 525.0);
  const float E6 = (float)(-1.0 / 40.0);
  const float ATOL = 1e-5f, RTOL = 1e-5f;

  for (int step = 0; step < NSTEPS; ++step) {
    if (done) break;
    const float* __restrict__ Yg = sel ? g_Yb : g_Ya;
    const float* __restrict__ Kg = sel ? g_Kb : g_Ka;
    float* __restrict__ Yo = sel ? g_Ya : g_Yb;
    float* __restrict__ Ko = sel ? g_Ka : g_Kb;
    const ull h2 = pack2(h_eff);

    /* ---- work-stealing tile loop (per warp-worker) ---- */
    unsigned tclaim = 0;
    if (lane == 0) tclaim = atomicAdd(&g_tctr[step], 1u);
    unsigned tt = __shfl_sync(0xffffffffu, tclaim, 0);

    while (tt < NTILE) {
      const size_t base = (size_t)tt * TSZ;

      /* own y, k1, k2 in registers */
      F4U yq[4], k1r[4], k2r[4], y5r[4], eac[4];
#pragma unroll
      for (int r = 0; r < 4; ++r) {
        yq[r]  = ld4cg(&Yg[base + og + r * DDIM]);
        k1r[r] = ld4cg(&Kg[base + og + r * DDIM]);
      }

      /* EARLY claim of next tile: 318-cyc atomic hides behind all 6 stages */
      unsigned nclaim = 0;
      if (lane == 0) nclaim = atomicAdd(&g_tctr[step], 1u);

      float acc[4][4];
      /* ---- stages 1..5 (fully unrolled; one warp-sync per stage) ---- */
#pragma unroll
      for (int st = 1; st <= 5; ++st) {
        float* syiW = (st & 1) ? syi1 : syi0;
        const ull c0 = pack2(cA[st - 1][0]);
        const ull c1 = pack2(cA[st - 1][1]);
#pragma unroll
        for (int r = 0; r < 4; ++r) {
          const int o = og + r * DDIM;
          ull s0 = mul2(c0, k1r[r].q[0]);
          ull s1 = mul2(c0, k1r[r].q[1]);
          if (st >= 2) {                      /* k2 from registers */
            s0 = fma2(c1, k2r[r].q[0], s0);
            s1 = fma2(c1, k2r[r].q[1], s1);
          }
#pragma unroll
          for (int m = 0; m < 3; ++m) {       /* k3..k_st from smem */
            if (m < st - 2) {
              const ull cm = pack2(cA[st - 1][m + 2]);
              F4U kv = ld4u(&sk[m * TSZ + o]);
              s0 = fma2(cm, kv.q[0], s0);
              s1 = fma2(cm, kv.q[1], s1);
            }
          }
          F4U yiv;
          yiv.q[0] = fma2(h2, s0, yq[r].q[0]);
          yiv.q[1] = fma2(h2, s1, yq[r].q[1]);
          st4u(&syiW[o], yiv);
        }
        __syncwarp();              /* syi writes visible within warp */

        gemm4x4(syiW, sW2, r0, cbg, acc);

        if (st == 1) {
#pragma unroll
          for (int r = 0; r < 4; ++r)
#pragma unroll
            for (int j = 0; j < 4; ++j) k2r[r].v[j] = fsin(-(acc[r][j] + bb.v[j]));
        } else {
#pragma unroll
          for (int r = 0; r < 4; ++r) {
            F4U kv;
#pragma unroll
            for (int j = 0; j < 4; ++j) kv.v[j] = fsin(-(acc[r][j] + bb.v[j]));
            st4u(&sk[(st - 2) * TSZ + og + r * DDIM], kv);   /* same-thread slot */
          }
        }
        /* no second sync: double-buffered syi + program order within warp */
      }

      /* ---- stage 6 (peeled, fused with error accumulation) ---- */
      {
        const ull C1 = pack2((float)(35.0 / 384.0));
        const ull C3 = pack2((float)(500.0 / 1113.0));
        const ull C4 = pack2((float)(125.0 / 192.0));
        const ull C5 = pack2((float)(-2187.0 / 6784.0));
        const ull C6 = pack2((float)(11.0 / 84.0));
        const ull F0 = pack2(E0), F2 = pack2(E2), F3 = pack2(E3);
        const ull F4c = pack2(E4), F5 = pack2(E5);
#pragma unroll
        for (int r = 0; r < 4; ++r) {
          const int o = og + r * DDIM;
          F4U k3 = ld4u(&sk[0 * TSZ + o]);
          F4U k4 = ld4u(&sk[1 * TSZ + o]);
          F4U k5 = ld4u(&sk[2 * TSZ + o]);
          F4U k6 = ld4u(&sk[3 * TSZ + o]);
#pragma unroll
          for (int q = 0; q < 2; ++q) {
            ull s = mul2(C1, k1r[r].q[q]);       /* B5: k2 coeff = 0 */
            s = fma2(C3, k3.q[q], s);
            s = fma2(C4, k4.q[q], s);
            s = fma2(C5, k5.q[q], s);
            s = fma2(C6, k6.q[q], s);
            y5r[r].q[q] = fma2(h2, s, yq[r].q[q]);
            ull e = mul2(F0, k1r[r].q[q]);       /* E1 = 0 */
            e = fma2(F2, k3.q[q], e);
            e = fma2(F3, k4.q[q], e);
            e = fma2(F4c, k5.q[q], e);
            e = fma2(F5, k6.q[q], e);
            eac[r].q[q] = e;
          }
          st4u(&syi0[o], y5r[r]);                /* y5 is stage-6 input (FSAL) */
          st4u(&Yo[base + o], y5r[r]);           /* candidate y5 out */
        }
        __syncwarp();

        gemm4x4(syi0, sW2, r0, cbg, acc);
      }

      /* k7 + error finalize + FSAL */
      double lsum = 0.0;
#pragma unroll
      for (int r = 0; r < 4; ++r) {
        const int o = og + r * DDIM;
        F4U k7;
#pragma unroll
        for (int j = 0; j < 4; ++j) k7.v[j] = fsin(-(acc[r][j] + bb.v[j]));
        st4u(&Ko[base + o], k7);
#pragma unroll
        for (int j = 0; j < 4; ++j) {
          float e = fmaf(E6, k7.v[j], eac[r].v[j]);
          e *= h_eff;
          float scale = fmaf(RTOL, fmaxf(fabsf(yq[r].v[j]), fabsf(y5r[r].v[j])), ATOL);
          float rr = e / scale;
          lsum += (double)(rr * rr);
        }
      }

      /* deterministic per-tile reduce (shuffles only); claim already done */
#pragma unroll
      for (int off = 16; off > 0; off >>= 1)
        lsum += __shfl_down_sync(0xffffffffu, lsum, off);
      if (lane == 0) g_tpart[tt] = lsum;
      tt = __shfl_sync(0xffffffffu, nclaim, 0);
    }
    /* single fence per step: order this warp's g_tpart stores before the
       block's grid-barrier arrival */
    if (lane == 0) __threadfence();

    /* ---- grid barrier ---- */
    ++nbar;
    __syncthreads();
    if (tid == 0) {
      __threadfence();
      unsigned old = atomicAdd(&g_count, 1u);
      if (old == PBLK - 1) { atomicExch(&g_count, 0u); __threadfence(); atomicExch(&g_release, nbar); }
      else { while (*((volatile unsigned*)&g_release) < nbar) { } }
      __threadfence();
    }
    __syncthreads();

    /* ---- deterministic control: fixed-order sum of 8192 tile partials ---- */
    double* sdd = (double*)(sm + OFF_H0);
    {
      double s = 0.0;
#pragma unroll
      for (int k = 0; k < 16; ++k) s += lddcg(&g_tpart[16 * tid + k]);
      sdd[tid] = s;
    }
    __syncthreads();
#pragma unroll
    for (int off = NTHR / 2; off > 0; off >>= 1) {
      if (tid < off) sdd[tid] += sdd[tid + off];
      __syncthreads();
    }
    const float err_norm = sqrtf((float)(sdd[0] / (double)((double)NROWS * (double)DDIM)));
    __syncthreads();

    /* exact reference control law (redundant in every thread/block) */
    const int accept = (err_norm <= 1.0f);
    if (accept) { t_now += h_eff; sel ^= 1; }
    float factor = 0.9f * powf(fmaxf(err_norm, 1e-10f), -0.2f);
    factor = fminf(fmaxf(factor, 0.2f), 10.0f);
    h = h_eff * factor;
    const float remaining = 5.0f - t_now;
    done = (remaining <= 0.0f) ? 1 : 0;
    h_eff = fminf(h, fmaxf(remaining, 1e-12f));
  }

  /* write accepted buffer to output (grid-stride, .cg: bypass stale L1) */
  const float* __restrict__ Yf = sel ? g_Yb : g_Ya;
  for (size_t i = (size_t)bid * NTHR + tid; i < (size_t)NROWS * DDIM / 4; i += (size_t)PBLK * NTHR) {
    F4U v = ld4cg(&Yf[i * 4]);
    st4u(&out[i * 4], v);
  }
}

extern "C" void kernel_launch(void* const* d_in, const int* in_sizes, int n_in,
                              void* d_out, int out_size) {
  const float* x = (const float*)d_in[0];
  const float* W = (const float*)d_in[1];
  const float* b = (const float*)d_in[2];
  float* out = (float*)d_out;

  cudaFuncSetAttribute(ode_kernel, cudaFuncAttributeMaxDynamicSharedMemorySize, SMEM_BYTES);

  init_kernel<<<1, 128>>>();
  ode_kernel<<<PBLK, NTHR, SMEM_BYTES>>>(x, W, b, out);
}

// round 15
// speedup vs baseline: 1.0898x; 1.0210x over previous
#include <cuda_runtime.h>
#include <math.h>

#define NROWS   65536
#define DDIM    64
#define TROWS   8             /* rows per tile */
#define NTILE   8192          /* NROWS / TROWS */
#define PBLK    148           /* persistent blocks, 1 per SM */
#define NTHR    512
#define NWORK   16            /* warp-workers per block */
#define NSTEPS  128
#define TSZ     512           /* TROWS * DDIM floats per tile */

/* shared memory layout (float offsets) */
#define OFF_SB    0            /* 64 : bias */
#define OFF_W2    80           /* 4096 : W repacked */
#define OFF_H0    4176         /* per-worker regions */
#define H_SYI0    0
#define H_SYI1    TSZ
#define H_SK      (2 * TSZ)             /* 3 slots (k4..k6) x 512 */
#define H_STRIDE  (5 * TSZ)
#define SMEM_FLOATS (OFF_H0 + NWORK * H_STRIDE)
#define SMEM_BYTES  (SMEM_FLOATS * 4)

typedef unsigned long long ull;

/* ---------------- persistent device state (no allocations) ---------------- */
__device__ float    g_Ya[NROWS * DDIM];
__device__ float    g_Yb[NROWS * DDIM];
__device__ float    g_Ka[NROWS * DDIM];
__device__ float    g_Kb[NROWS * DDIM];
__device__ double   g_tpart[NTILE];
__device__ unsigned g_tctr[NSTEPS];
__device__ unsigned g_count;
__device__ unsigned g_release;

/* Dormand-Prince A coefficients (exact float32 of rationals) */
__constant__ float cA[6][6] = {
  { (float)(1.0/5.0), 0.f, 0.f, 0.f, 0.f, 0.f },
  { (float)(3.0/40.0), (float)(9.0/40.0), 0.f, 0.f, 0.f, 0.f },
  { (float)(44.0/45.0), (float)(-56.0/15.0), (float)(32.0/9.0), 0.f, 0.f, 0.f },
  { (float)(19372.0/6561.0), (float)(-25360.0/2187.0), (float)(64448.0/6561.0), (float)(-212.0/729.0), 0.f, 0.f },
  { (float)(9017.0/3168.0), (float)(-355.0/33.0), (float)(46732.0/5247.0), (float)(49.0/176.0), (float)(-5103.0/18656.0), 0.f },
  { (float)(35.0/384.0), 0.f, (float)(500.0/1113.0), (float)(125.0/192.0), (float)(-2187.0/6784.0), (float)(11.0/84.0) },
};

union F4U {
  float v[4];
  ull   q[2];
  float4 f4;
};

__device__ __forceinline__ F4U ld4u(const float* p) { F4U r; r.f4 = *(const float4*)p; return r; }
__device__ __forceinline__ void st4u(float* p, const F4U a) { *(float4*)p = a.f4; }
__device__ __forceinline__ F4U ld4cg(const float* p) {
  F4U r;
  asm volatile("ld.global.cg.v4.f32 {%0,%1,%2,%3}, [%4];"
               : "=f"(r.v[0]), "=f"(r.v[1]), "=f"(r.v[2]), "=f"(r.v[3]) : "l"(p));
  return r;
}
__device__ __forceinline__ double lddcg(const double* p) {
  double r;
  asm volatile("ld.global.cg.f64 %0, [%1];" : "=d"(r) : "l"(p));
  return r;
}

/* packed fp32x2 ops (Blackwell) */
__device__ __forceinline__ ull fma2(ull a, ull b, ull c) {
  ull d; asm("fma.rn.f32x2 %0, %1, %2, %3;" : "=l"(d) : "l"(a), "l"(b), "l"(c)); return d;
}
__device__ __forceinline__ ull mul2(ull a, ull b) {
  ull d; asm("mul.rn.f32x2 %0, %1, %2;" : "=l"(d) : "l"(a), "l"(b)); return d;
}
__device__ __forceinline__ ull pack2(float x) {
  ull d; asm("mov.b64 %0, {%1, %1};" : "=l"(d) : "f"(x)); return d;
}
__device__ __forceinline__ void unpack2(ull v, float& lo, float& hi) {
  asm("mov.b64 {%0, %1}, %2;" : "=f"(lo), "=f"(hi) : "l"(v));
}
/* fast sin: args O(1..10); abs err ~2^-21, far below 1e-3 tolerance */
__device__ __forceinline__ float fsin(float x) {
  float r; asm("sin.approx.f32 %0, %1;" : "=f"(r) : "f"(x)); return r;
}

/* 4x4-output 64-k GEMM via fma.rn.f32x2 (R12/R14 layout — validated best). */
__device__ __forceinline__ void gemm4x4(const float* __restrict__ sa,
                                        const float* __restrict__ sW2,
                                        int r0, int cbg, float accf[4][4]) {
  ull acc[4][4];
#pragma unroll
  for (int i = 0; i < 4; ++i)
#pragma unroll
    for (int j = 0; j < 4; ++j) acc[i][j] = 0ull;

  const float* ap = sa + r0 * DDIM;
#pragma unroll
  for (int k4 = 0; k4 < 16; ++k4) {
    ulonglong2 av[4];
#pragma unroll
    for (int i = 0; i < 4; ++i)
      av[i] = *(const ulonglong2*)(ap + i * DDIM + k4 * 4);
#pragma unroll
    for (int hh = 0; hh < 2; ++hh) {
      const int k2i = k4 * 2 + hh;
      ulonglong2 w01 = *(const ulonglong2*)(sW2 + k2i * 128 + cbg * 4);
      ulonglong2 w23 = *(const ulonglong2*)(sW2 + k2i * 128 + 64 + cbg * 4);
#pragma unroll
      for (int i = 0; i < 4; ++i) {
        ull a = hh ? av[i].y : av[i].x;
        acc[i][0] = fma2(a, w01.x, acc[i][0]);
        acc[i][1] = fma2(a, w01.y, acc[i][1]);
        acc[i][2] = fma2(a, w23.x, acc[i][2]);
        acc[i][3] = fma2(a, w23.y, acc[i][3]);
      }
    }
  }
#pragma unroll
  for (int i = 0; i < 4; ++i)
#pragma unroll
    for (int j = 0; j < 4; ++j) {
      float lo, hi; unpack2(acc[i][j], lo, hi);
      accf[i][j] = lo + hi;
    }
}

__global__ void init_kernel() {
  if (threadIdx.x == 0) { g_count = 0u; g_release = 0u; }
  if (threadIdx.x < NSTEPS) g_tctr[threadIdx.x] = 0u;
}

/* ---------------- the whole solve in one persistent kernel ---------------- */
__global__ void __launch_bounds__(NTHR, 1) ode_kernel(const float* __restrict__ x,
                                                      const float* __restrict__ W,
                                                      const float* __restrict__ b,
                                                      float* __restrict__ out) {
  extern __shared__ float sm[];
  float* sb  = sm + OFF_SB;
  float* sW2 = sm + OFF_W2;

  const int tid = threadIdx.x, bid = blockIdx.x;
  const int wrk = tid >> 5, lane = tid & 31;      /* warp-worker id, lane */
  float* smq  = sm + OFF_H0 + wrk * H_STRIDE;
  float* syi0 = smq + H_SYI0;
  float* syi1 = smq + H_SYI1;
  float* sk   = smq + H_SK;          /* slots: 0=k4 1=k5 2=k6 */

  const int r0  = (lane >> 4) << 2;      /* rows r0..r0+3 (0 or 4) */
  const int cbg = lane & 15;             /* cols cbg*4..+3 */
  const int og  = r0 * DDIM + cbg * 4;   /* own base offset within tile */

  if (tid < 16) st4u(&sb[tid * 4], ld4u(&b[tid * 4]));
  /* repack W into k-pair-major layout (validated R3-R14) */
  for (int p = tid; p < 2048; p += NTHR) {
    const int k2i = p >> 6, j = p & 63;
    const int cbb = j >> 2, jr = j & 3;
    const int pos = k2i * 128 + ((jr >= 2) ? 64 : 0) + cbb * 4 + (jr & 1) * 2;
    sW2[pos]     = W[j * DDIM + 2 * k2i];
    sW2[pos + 1] = W[j * DDIM + 2 * k2i + 1];
  }
  __syncthreads();
  const F4U bb = ld4u(&sb[cbg * 4]);

  /* prologue: Ya = x ; Ka = k1 = f(x).  Static tiles per warp-worker. */
  for (int t = bid * NWORK + wrk; t < NTILE; t += PBLK * NWORK) {
    const size_t base = (size_t)t * TSZ;
    for (int i = lane; i < TSZ / 4; i += 32) {
      F4U v = ld4u(&x[base + i * 4]);
      st4u(&syi0[i * 4], v);
      st4u(&g_Ya[base + i * 4], v);
    }
    __syncwarp();
    float acc[4][4];
    gemm4x4(syi0, sW2, r0, cbg, acc);
#pragma unroll
    for (int r = 0; r < 4; ++r) {
      F4U kv;
#pragma unroll
      for (int j = 0; j < 4; ++j) kv.v[j] = fsin(-(acc[r][j] + bb.v[j]));
      st4u(&g_Ka[base + og + r * DDIM], kv);
    }
    __syncwarp();
  }

  unsigned nbar = 1;
  __syncthreads();
  if (tid == 0) {
    __threadfence();
    unsigned old = atomicAdd(&g_count, 1u);
    if (old == PBLK - 1) { atomicExch(&g_count, 0u); __threadfence(); atomicExch(&g_release, nbar); }
    else { while (*((volatile unsigned*)&g_release) < nbar) { } }
    __threadfence();
  }
  __syncthreads();

  float t_now = 0.0f, h = 0.01f, h_eff = 0.01f;
  int sel = 0, done = 0;

  const float E0 = (float)(71.0 / 57600.0);
  const float E2 = (float)(-71.0 / 16695.0);
  const float E3 = (float)(71.0 / 1920.0);
  const float E4 = (float)(-17253.0 / 339200.0);
  const float E5 = (float)(22.0 / 525.0);
  const float E6 = (float)(-1.0 / 40.0);
  const float ATOL = 1e-5f, RTOL = 1e-5f;

  for (int step = 0; step < NSTEPS; ++step) {
    if (done) break;
    const float* __restrict__ Yg = sel ? g_Yb : g_Ya;
    const float* __restrict__ Kg = sel ? g_Kb : g_Ka;
    float* __restrict__ Yo = sel ? g_Ya : g_Yb;
    float* __restrict__ Ko = sel ? g_Ka : g_Kb;
    const ull h2 = pack2(h_eff);

    /* ---- work-stealing tile loop (per warp-worker) ---- */
    unsigned tclaim = 0;
    if (lane == 0) tclaim = atomicAdd(&g_tctr[step], 1u);
    unsigned tt = __shfl_sync(0xffffffffu, tclaim, 0);
    /* first claims are < PBLK*NWORK (2368) < NTILE: load unconditionally */
    F4U yq[4], k1r[4], k2r[4], k3r[4], eac[4];
#pragma unroll
    for (int r = 0; r < 4; ++r) {
      yq[r]  = ld4cg(&Yg[(size_t)tt * TSZ + og + r * DDIM]);
      k1r[r] = ld4cg(&Kg[(size_t)tt * TSZ + og + r * DDIM]);
    }

    while (tt < NTILE) {
      const size_t base = (size_t)tt * TSZ;

      /* EARLY claim of next tile: 318-cyc atomic hides behind all 6 stages */
      unsigned nclaim = 0;
      if (lane == 0) nclaim = atomicAdd(&g_tctr[step], 1u);

      float acc[4][4];
      /* ---- stages 1..5 (fully unrolled; one warp-sync per stage) ---- */
#pragma unroll
      for (int st = 1; st <= 5; ++st) {
        float* syiW = (st & 1) ? syi1 : syi0;
        const ull c0 = pack2(cA[st - 1][0]);
        const ull c1 = pack2(cA[st - 1][1]);
        const ull c2 = pack2(cA[st - 1][2]);
#pragma unroll
        for (int r = 0; r < 4; ++r) {
          const int o = og + r * DDIM;
          ull s0 = mul2(c0, k1r[r].q[0]);
          ull s1 = mul2(c0, k1r[r].q[1]);
          if (st >= 2) {                      /* k2 from registers */
            s0 = fma2(c1, k2r[r].q[0], s0);
            s1 = fma2(c1, k2r[r].q[1], s1);
          }
          if (st >= 3) {                      /* k3 from registers */
            s0 = fma2(c2, k3r[r].q[0], s0);
            s1 = fma2(c2, k3r[r].q[1], s1);
          }
#pragma unroll
          for (int m = 0; m < 2; ++m) {       /* k4..k_st from smem */
            if (m < st - 3) {
              const ull cm = pack2(cA[st - 1][m + 3]);
              F4U kv = ld4u(&sk[m * TSZ + o]);
              s0 = fma2(cm, kv.q[0], s0);
              s1 = fma2(cm, kv.q[1], s1);
            }
          }
          F4U yiv;
          yiv.q[0] = fma2(h2, s0, yq[r].q[0]);
          yiv.q[1] = fma2(h2, s1, yq[r].q[1]);
          st4u(&syiW[o], yiv);
        }
        __syncwarp();              /* syi writes visible within warp */

        gemm4x4(syiW, sW2, r0, cbg, acc);

        if (st == 1) {
#pragma unroll
          for (int r = 0; r < 4; ++r)
#pragma unroll
            for (int j = 0; j < 4; ++j) k2r[r].v[j] = fsin(-(acc[r][j] + bb.v[j]));
        } else if (st == 2) {
#pragma unroll
          for (int r = 0; r < 4; ++r)
#pragma unroll
            for (int j = 0; j < 4; ++j) k3r[r].v[j] = fsin(-(acc[r][j] + bb.v[j]));
        } else {
#pragma unroll
          for (int r = 0; r < 4; ++r) {
            F4U kv;
#pragma unroll
            for (int j = 0; j < 4; ++j) kv.v[j] = fsin(-(acc[r][j] + bb.v[j]));
            st4u(&sk[(st - 3) * TSZ + og + r * DDIM], kv);   /* k_{st+1}, slot st-3 */
          }
        }
        /* no second sync: double-buffered syi + program order within warp */
      }

      /* ---- stage 6 (peeled, fused with error accumulation) ---- */
      {
        const ull C1 = pack2((float)(35.0 / 384.0));
        const ull C3 = pack2((float)(500.0 / 1113.0));
        const ull C4 = pack2((float)(125.0 / 192.0));
        const ull C5 = pack2((float)(-2187.0 / 6784.0));
        const ull C6 = pack2((float)(11.0 / 84.0));
        const ull F0 = pack2(E0), F2 = pack2(E2), F3 = pack2(E3);
        const ull F4c = pack2(E4), F5 = pack2(E5);
#pragma unroll
        for (int r = 0; r < 4; ++r) {
          const int o = og + r * DDIM;
          F4U k4 = ld4u(&sk[0 * TSZ + o]);
          F4U k5 = ld4u(&sk[1 * TSZ + o]);
          F4U k6 = ld4u(&sk[2 * TSZ + o]);
          F4U y5v;
#pragma unroll
          for (int q = 0; q < 2; ++q) {
            ull s = mul2(C1, k1r[r].q[q]);       /* B5: k2 coeff = 0 */
            s = fma2(C3, k3r[r].q[q], s);
            s = fma2(C4, k4.q[q], s);
            s = fma2(C5, k5.q[q], s);
            s = fma2(C6, k6.q[q], s);
            y5v.q[q] = fma2(h2, s, yq[r].q[q]);
            ull e = mul2(F0, k1r[r].q[q]);       /* E1 = 0 */
            e = fma2(F2, k3r[r].q[q], e);
            e = fma2(F3, k4.q[q], e);
            e = fma2(F4c, k5.q[q], e);
            e = fma2(F5, k6.q[q], e);
            eac[r].q[q] = e;
          }
          st4u(&syi0[o], y5v);                   /* y5 is stage-6 input (FSAL) */
          st4u(&Yo[base + o], y5v);              /* candidate y5 out */
        }
        __syncwarp();

        gemm4x4(syi0, sW2, r0, cbg, acc);
      }

      /* k7 + error finalize + FSAL; y5 reloaded from syi0 */
      double lsum = 0.0;
#pragma unroll
      for (int r = 0; r < 4; ++r) {
        const int o = og + r * DDIM;
        F4U k7;
#pragma unroll
        for (int j = 0; j < 4; ++j) k7.v[j] = fsin(-(acc[r][j] + bb.v[j]));
        st4u(&Ko[base + o], k7);
        F4U y5v = ld4u(&syi0[o]);
#pragma unroll
        for (int j = 0; j < 4; ++j) {
          float e = fmaf(E6, k7.v[j], eac[r].v[j]);
          e *= h_eff;
          float scale = fmaf(RTOL, fmaxf(fabsf(yq[r].v[j]), fabsf(y5v.v[j])), ATOL);
          float rr = e / scale;
          lsum += (double)(rr * rr);
        }
      }

      /* next-tile prefetch: overlap y/k1 L2 round-trip with the reduce */
      const unsigned nx = __shfl_sync(0xffffffffu, nclaim, 0);
      if (nx < NTILE) {
        const size_t nb = (size_t)nx * TSZ;
#pragma unroll
        for (int r = 0; r < 4; ++r) {
          yq[r]  = ld4cg(&Yg[nb + og + r * DDIM]);
          k1r[r] = ld4cg(&Kg[nb + og + r * DDIM]);
        }
      }

      /* deterministic per-tile reduce (shuffles only) */
#pragma unroll
      for (int off = 16; off > 0; off >>= 1)
        lsum += __shfl_down_sync(0xffffffffu, lsum, off);
      if (lane == 0) g_tpart[tt] = lsum;
      tt = nx;
    }
    /* single fence per step: order this warp's g_tpart stores before the
       block's grid-barrier arrival */
    if (lane == 0) __threadfence();

    /* ---- grid barrier ---- */
    ++nbar;
    __syncthreads();
    if (tid == 0) {
      __threadfence();
      unsigned old = atomicAdd(&g_count, 1u);
      if (old == PBLK - 1) { atomicExch(&g_count, 0u); __threadfence(); atomicExch(&g_release, nbar); }
      else { while (*((volatile unsigned*)&g_release) < nbar) { } }
      __threadfence();
    }
    __syncthreads();

    /* ---- deterministic control: fixed-order sum of 8192 tile partials ---- */
    double* sdd = (double*)(sm + OFF_H0);
    {
      double s = 0.0;
#pragma unroll
      for (int k = 0; k < 16; ++k) s += lddcg(&g_tpart[16 * tid + k]);
      sdd[tid] = s;
    }
    __syncthreads();
#pragma unroll
    for (int off = NTHR / 2; off > 0; off >>= 1) {
      if (tid < off) sdd[tid] += sdd[tid + off];
      __syncthreads();
    }
    const float err_norm = sqrtf((float)(sdd[0] / (double)((double)NROWS * (double)DDIM)));
    __syncthreads();

    /* exact reference control law (redundant in every thread/block) */
    const int accept = (err_norm <= 1.0f);
    if (accept) { t_now += h_eff; sel ^= 1; }
    float factor = 0.9f * powf(fmaxf(err_norm, 1e-10f), -0.2f);
    factor = fminf(fmaxf(factor, 0.2f), 10.0f);
    h = h_eff * factor;
    const float remaining = 5.0f - t_now;
    done = (remaining <= 0.0f) ? 1 : 0;
    h_eff = fminf(h, fmaxf(remaining, 1e-12f));
  }

  /* write accepted buffer to output (grid-stride, .cg: bypass stale L1) */
  const float* __restrict__ Yf = sel ? g_Yb : g_Ya;
  for (size_t i = (size_t)bid * NTHR + tid; i < (size_t)NROWS * DDIM / 4; i += (size_t)PBLK * NTHR) {
    F4U v = ld4cg(&Yf[i * 4]);
    st4u(&out[i * 4], v);
  }
}

extern "C" void kernel_launch(void* const* d_in, const int* in_sizes, int n_in,
                              void* d_out, int out_size) {
  const float* x = (const float*)d_in[0];
  const float* W = (const float*)d_in[1];
  const float* b = (const float*)d_in[2];
  float* out = (float*)d_out;

  cudaFuncSetAttribute(ode_kernel, cudaFuncAttributeMaxDynamicSharedMemorySize, SMEM_BYTES);

  init_kernel<<<1, 128>>>();
  ode_kernel<<<PBLK, NTHR, SMEM_BYTES>>>(x, W, b, out);
}